// round 13
// baseline (speedup 1.0000x reference)
#include <cuda_runtime.h>
#include <cuda_fp16.h>
#include <stdint.h>

#define B_ 2
#define N_ 512
#define IN_DIM 512
#define EMB 64
#define HID 128
#define NPOS 1025

// ---------------- device scratch (no cudaMalloc allowed) ----------------
__device__ float g_sl[B_ * N_ * EMB];
__device__ float g_P[NPOS * HID];
__device__ float g_W1Tf[HID * EMB];            // fp32 W1_top^T [j][d]
__device__ unsigned short g_W2Th[EMB * HID];   // fp16(W2^T) [o][j]
// SR pre-split into mma fragment layout: [b][mb(32)][lane(32)][16 words]
__device__ uint32_t g_srfh[B_ * 32 * 32 * 16];
__device__ uint32_t g_srfl[B_ * 32 * 32 * 16];

// ---------------- helpers ----------------
__device__ __forceinline__ uint32_t smem_u32_of(const void* p) {
    uint32_t a;
    asm("{ .reg .u64 t; cvta.to.shared.u64 t, %1; cvt.u32.u64 %0, t; }"
        : "=r"(a) : "l"(p));
    return a;
}
// fp16 hi/lo split of a float pair -> (hi_half2, lo_half2)
__device__ __forceinline__ uint2 split2h(float e0, float e1) {
    __half2 h = __floats2half2_rn(e0, e1);
    float f0 = __half2float(__low2half(h));
    float f1 = __half2float(__high2half(h));
    __half2 lo = __floats2half2_rn(e0 - f0, e1 - f1);
    return make_uint2(*reinterpret_cast<uint32_t*>(&h),
                      *reinterpret_cast<uint32_t*>(&lo));
}
__device__ __forceinline__ void mma16816(float* c, const uint32_t* a,
                                         uint32_t b0, uint32_t b1) {
    asm volatile(
        "mma.sync.aligned.m16n8k16.row.col.f32.f16.f16.f32 "
        "{%0,%1,%2,%3}, {%4,%5,%6,%7}, {%8,%9}, {%0,%1,%2,%3};"
        : "+f"(c[0]), "+f"(c[1]), "+f"(c[2]), "+f"(c[3])
        : "r"(a[0]), "r"(a[1]), "r"(a[2]), "r"(a[3]), "r"(b0), "r"(b1));
}
__device__ __forceinline__ void ldsm4(uint32_t* r, uint32_t addr) {
    asm volatile("ldmatrix.sync.aligned.m8n8.x4.shared.b16 {%0,%1,%2,%3}, [%4];"
                 : "=r"(r[0]), "=r"(r[1]), "=r"(r[2]), "=r"(r[3]) : "r"(addr));
}

// ---------------- kernel 1: projections + fused SR fragment emit ----------------
// 64 blocks x 16 rows (= one mb tile each), 256 threads.
__global__ void proj2_kernel(const float* __restrict__ s,
                             const float* __restrict__ Wl, const float* __restrict__ bl,
                             const float* __restrict__ Wr, const float* __restrict__ br) {
    extern __shared__ float psm[];
    float* SsT   = psm;                  // [512][20]
    float* Wc    = psm + 512 * 20;       // [64][128]
    float* srbuf = psm + 512 * 20 + 64 * 128;  // [16][64] SR tile

    const int t = threadIdx.x;
    const int r0 = blockIdx.x * 16;

    for (int i = t; i < 16 * IN_DIM; i += 256) {
        int row = i >> 9, k = i & 511;
        SsT[k * 20 + row] = s[(size_t)(r0 + row) * IN_DIM + k];
    }

    const int col = t & 127, rg = t >> 7;
    float acc[8];
    const float bias = (col < 64) ? bl[col] : br[col - 64];
#pragma unroll
    for (int r = 0; r < 8; r++) acc[r] = bias;
    __syncthreads();

    for (int kt = 0; kt < 8; kt++) {
        for (int i = t; i < 64 * 128; i += 256) {
            int k = i >> 7, c = i & 127;
            Wc[i] = (c < 64) ? Wl[(size_t)(kt * 64 + k) * 64 + c]
                             : Wr[(size_t)(kt * 64 + k) * 64 + (c - 64)];
        }
        __syncthreads();
#pragma unroll 4
        for (int k = 0; k < 64; k++) {
            float w = Wc[k * 128 + col];
            const float* sp = &SsT[(kt * 64 + k) * 20 + rg * 8];
            float4 a0 = *(const float4*)sp;
            float4 a1 = *(const float4*)(sp + 4);
            acc[0] += a0.x * w; acc[1] += a0.y * w; acc[2] += a0.z * w; acc[3] += a0.w * w;
            acc[4] += a1.x * w; acc[5] += a1.y * w; acc[6] += a1.z * w; acc[7] += a1.w * w;
        }
        __syncthreads();
    }

    // left half -> g_sl (DRAM); right half -> srbuf (smem)
#pragma unroll
    for (int r = 0; r < 8; r++) {
        int lrow = rg * 8 + r;
        if (col < 64) g_sl[(size_t)(r0 + lrow) * 64 + col] = acc[r];
        else          srbuf[lrow * 64 + (col - 64)] = acc[r];
    }
    __syncthreads();

    // emit fragment-layout fp16 hi/lo for this mb tile (512 (l,r) items, 2/thread)
    {
        const int bb = blockIdx.x >> 5, mb = blockIdx.x & 31;
        uint32_t* oh = g_srfh + (((size_t)bb * 32 + mb) * 32) * 16;
        uint32_t* ol = g_srfl + (((size_t)bb * 32 + mb) * 32) * 16;
#pragma unroll
        for (int it = 0; it < 2; it++) {
            int idx = t + it * 256;          // = l*16 + r
            int l = idx >> 4, r = idx & 15;
            int tt = r >> 2, e = r & 3;
            int lrow = (l >> 2) + (e & 1) * 8;
            int c = (l & 3) * 2 + 16 * tt + (e & 2) * 4;
            uint2 sp = split2h(srbuf[lrow * 64 + c], srbuf[lrow * 64 + c + 1]);
            oh[idx] = sp.x;
            ol[idx] = sp.y;
        }
    }
}

// ---------------- kernel 2: positional table + fused weight transposes ----------------
__global__ void pos_kernel(const float* __restrict__ emb,
                           const float* __restrict__ W1,
                           const float* __restrict__ b1,
                           const float* __restrict__ W2) {
    __shared__ float erow[EMB];
    const int dist = blockIdx.x;
    const int h = threadIdx.x;

    // fused prep: blocks 0..63 also transpose W1-top / W2 (8192 items total)
    if (blockIdx.x < 64) {
        int i = blockIdx.x * 128 + h;
        {
            int j = i >> 6, d = i & 63;
            g_W1Tf[i] = W1[d * HID + j];
        }
        {
            int o = i & 63, jj = i >> 6;
            g_W2Th[o * HID + jj] = __half_as_ushort(__float2half_rn(W2[jj * EMB + o]));
        }
    }

    if (h < EMB) erow[h] = emb[dist * EMB + h];
    __syncthreads();
    float acc = b1[h];
#pragma unroll
    for (int d = 0; d < EMB; d++)
        acc = fmaf(erow[d], W1[(EMB + d) * HID + h], acc);
    g_P[dist * HID + h] = acc;
}

// ---------------- main kernel: folded-B1, coalesced A-frag LDG, 2 CTAs ----------------
// smem: sl 256B | b2 256B | W1' [128 j][72 fp16] 144B-stride | W2 [64 o][136] 272B-stride
#define OFF_SL   0
#define OFF_B2S  256
#define OFF_W1   512
#define OFF_W2   (OFF_W1 + 18432)
#define SMEM_MAIN (OFF_W2 + 17408)   // 36352 bytes

__global__ __launch_bounds__(256, 2)
void pair_mma_kernel(const float* __restrict__ b2, float* __restrict__ out) {
    extern __shared__ char sm[];
    const uint32_t smb = smem_u32_of(sm);
    const int tid = threadIdx.x;
    const int w = tid >> 5, l = tid & 31;
    const int n = blockIdx.x, b = blockIdx.y;

    float* sl = (float*)(sm + OFF_SL);
    float* b2s = (float*)(sm + OFF_B2S);
    if (tid < 64) {
        sl[tid] = g_sl[((size_t)b * N_ + n) * EMB + tid];
        b2s[tid] = b2[tid];
    }
    for (int i = tid; i < 2048; i += 256) {
        int o = i >> 5, j8 = (i & 31) * 8;
        *(uint2*)(sm + OFF_W2 + o * 272 + j8) = ((const uint2*)g_W2Th)[i];
    }
    __syncthreads();   // sl ready for the fold below

    // build B1'[j][d] = fp16(W1^T[j][d] * sl[d]) into smem (ldsm layout)
    for (int g = tid; g < 2048; g += 256) {
        int j = g >> 4, d0 = (g & 15) * 4;
        float4 wv = *(const float4*)(g_W1Tf + j * 64 + d0);
        float4 sv = *(const float4*)(sl + d0);
        __half2 h0 = __floats2half2_rn(wv.x * sv.x, wv.y * sv.y);
        __half2 h1 = __floats2half2_rn(wv.z * sv.z, wv.w * sv.w);
        *(uint2*)(sm + OFF_W1 + j * 144 + d0 * 2) =
            make_uint2(*reinterpret_cast<uint32_t*>(&h0),
                       *reinterpret_cast<uint32_t*>(&h1));
    }
    __syncthreads();   // smem read-only below: mt loop has NO barriers

    // ---- per-thread ldmatrix base addresses for B operands (x4 forms) ----
    const uint32_t preB1 = smb + OFF_W1 +
        ((l & 7) + ((l >> 4) << 3)) * 144 + ((l >> 3) & 1) * 16;
    const uint32_t preB2 = smb + OFF_W2 +
        ((l & 7) + ((l >> 4) << 3)) * 272 + ((l >> 3) & 1) * 16;

    const int fc0 = (l & 3) * 2;
    const int fr0 = 16 * w + (l >> 2);

    for (int mt = 0; mt < 4; mt++) {
        const int m_t = mt * 128 + fr0;
        const int mb = mt * 8 + w;

        // ---- A fragments: pure coalesced LDG.128 (pre-split in proj2) ----
        uint4 hv[4], lv[4];
        {
            const uint4* hp = (const uint4*)(g_srfh +
                ((((size_t)b * 32 + mb) * 32 + l) * 16));
            const uint4* lp = (const uint4*)(g_srfl +
                ((((size_t)b * 32 + mb) * 32 + l) * 16));
#pragma unroll
            for (int t = 0; t < 4; t++) { hv[t] = hp[t]; lv[t] = lp[t]; }
        }

        // ---- GEMM1: H[16,128] per warp = SR @ B1'^T, 2-term fp16 ----
        float D1[16][4];
#pragma unroll
        for (int q = 0; q < 16; q++)
#pragma unroll
            for (int e = 0; e < 4; e++) D1[q][e] = 0.0f;

#pragma unroll
        for (int t = 0; t < 4; t++) {
#pragma unroll
            for (int qq = 0; qq < 8; qq++) {
                uint32_t bh[4];
                ldsm4(bh, preB1 + qq * 2304 + t * 32);
                mma16816(D1[2 * qq],     (const uint32_t*)&hv[t], bh[0], bh[1]);
                mma16816(D1[2 * qq + 1], (const uint32_t*)&hv[t], bh[2], bh[3]);
                mma16816(D1[2 * qq],     (const uint32_t*)&lv[t], bh[0], bh[1]);
                mma16816(D1[2 * qq + 1], (const uint32_t*)&lv[t], bh[2], bh[3]);
            }
        }

        // ---- relu(H + P[dist]) in registers ----
        {
            const float* P0 = g_P + (size_t)(n - m_t + 512) * HID;
            const float* P1 = P0 - 8 * HID;   // row m_t+8
#pragma unroll
            for (int q = 0; q < 16; q++) {
                const int jc = 8 * q + fc0;
                float2 p0 = __ldg((const float2*)(P0 + jc));
                float2 p1 = __ldg((const float2*)(P1 + jc));
                D1[q][0] = fmaxf(D1[q][0] + p0.x, 0.0f);
                D1[q][1] = fmaxf(D1[q][1] + p0.y, 0.0f);
                D1[q][2] = fmaxf(D1[q][2] + p1.x, 0.0f);
                D1[q][3] = fmaxf(D1[q][3] + p1.y, 0.0f);
            }
        }

        // ---- GEMM2: out = Hrelu @ W2, 2-term fp16 (A from registers) ----
        float D2[8][4];
#pragma unroll
        for (int q = 0; q < 8; q++)
#pragma unroll
            for (int e = 0; e < 4; e++) D2[q][e] = 0.0f;

#pragma unroll
        for (int t2 = 0; t2 < 8; t2++) {
            uint32_t ah2[4], al2[4];
            {
                uint2 s0 = split2h(D1[2 * t2][0],     D1[2 * t2][1]);
                uint2 s1 = split2h(D1[2 * t2][2],     D1[2 * t2][3]);
                uint2 s2 = split2h(D1[2 * t2 + 1][0], D1[2 * t2 + 1][1]);
                uint2 s3 = split2h(D1[2 * t2 + 1][2], D1[2 * t2 + 1][3]);
                ah2[0] = s0.x; al2[0] = s0.y;
                ah2[1] = s1.x; al2[1] = s1.y;
                ah2[2] = s2.x; al2[2] = s2.y;
                ah2[3] = s3.x; al2[3] = s3.y;
            }
#pragma unroll
            for (int qq = 0; qq < 4; qq++) {
                uint32_t bh[4];
                ldsm4(bh, preB2 + qq * 4352 + t2 * 32);
                mma16816(D2[2 * qq],     ah2, bh[0], bh[1]);
                mma16816(D2[2 * qq + 1], ah2, bh[2], bh[3]);
                mma16816(D2[2 * qq],     al2, bh[0], bh[1]);
                mma16816(D2[2 * qq + 1], al2, bh[2], bh[3]);
            }
        }

        // ---- epilogue: + b2 (from smem), store fp32 ----
        {
            float* ob = out + (((size_t)b * N_ + n) * N_ + m_t) * EMB;
#pragma unroll
            for (int q = 0; q < 8; q++) {
                const int oc = 8 * q + fc0;
                float2 bb = *(const float2*)(b2s + oc);
                *(float2*)(ob + oc) =
                    make_float2(D2[q][0] + bb.x, D2[q][1] + bb.y);
                *(float2*)(ob + 8 * EMB + oc) =
                    make_float2(D2[q][2] + bb.x, D2[q][3] + bb.y);
            }
        }
    }
}

// ---------------- launch ----------------
extern "C" void kernel_launch(void* const* d_in, const int* in_sizes, int n_in,
                              void* d_out, int out_size) {
    const float* s       = (const float*)d_in[0];
    const float* W_left  = (const float*)d_in[1];
    const float* b_left  = (const float*)d_in[2];
    const float* W_right = (const float*)d_in[3];
    const float* b_right = (const float*)d_in[4];
    const float* emb     = (const float*)d_in[5];
    const float* W1      = (const float*)d_in[6];
    const float* b1      = (const float*)d_in[7];
    const float* W2      = (const float*)d_in[8];
    const float* b2      = (const float*)d_in[9];
    float* out = (float*)d_out;

    const int proj_smem = (512 * 20 + 64 * 128 + 16 * 64) * sizeof(float);  // 77824
    cudaFuncSetAttribute(proj2_kernel,
                         cudaFuncAttributeMaxDynamicSharedMemorySize, proj_smem);
    cudaFuncSetAttribute(pair_mma_kernel,
                         cudaFuncAttributeMaxDynamicSharedMemorySize, SMEM_MAIN);

    proj2_kernel<<<64, 256, proj_smem>>>(s, W_left, b_left, W_right, b_right);
    pos_kernel<<<NPOS, 128>>>(emb, W1, b1, W2);
    pair_mma_kernel<<<dim3(N_, B_), 256, SMEM_MAIN>>>(b2, out);
}

// round 14
// speedup vs baseline: 1.2908x; 1.2908x over previous
#include <cuda_runtime.h>
#include <cuda_fp16.h>
#include <stdint.h>

#define B_ 2
#define N_ 512
#define IN_DIM 512
#define EMB 64
#define HID 128
#define NPOS 1025

// ---------------- device scratch (no cudaMalloc allowed) ----------------
__device__ float g_sl[B_ * N_ * EMB];
__device__ float g_P[NPOS * HID];
__device__ float g_W1Tf[HID * EMB];            // fp32 W1_top^T [j][d]
__device__ unsigned short g_W2Th[EMB * HID];   // fp16(W2^T) [o][j]
// SR pre-split into mma fragment layout: [b][mb(32)][lane(32)][16 words]
__device__ uint32_t g_srfh[B_ * 32 * 32 * 16];
__device__ uint32_t g_srfl[B_ * 32 * 32 * 16];

// ---------------- helpers ----------------
__device__ __forceinline__ uint32_t smem_u32_of(const void* p) {
    uint32_t a;
    asm("{ .reg .u64 t; cvta.to.shared.u64 t, %1; cvt.u32.u64 %0, t; }"
        : "=r"(a) : "l"(p));
    return a;
}
// fp16 hi/lo split of a float pair -> (hi_half2, lo_half2)
__device__ __forceinline__ uint2 split2h(float e0, float e1) {
    __half2 h = __floats2half2_rn(e0, e1);
    float f0 = __half2float(__low2half(h));
    float f1 = __half2float(__high2half(h));
    __half2 lo = __floats2half2_rn(e0 - f0, e1 - f1);
    return make_uint2(*reinterpret_cast<uint32_t*>(&h),
                      *reinterpret_cast<uint32_t*>(&lo));
}
__device__ __forceinline__ void mma16816(float* c, const uint32_t* a,
                                         uint32_t b0, uint32_t b1) {
    asm volatile(
        "mma.sync.aligned.m16n8k16.row.col.f32.f16.f16.f32 "
        "{%0,%1,%2,%3}, {%4,%5,%6,%7}, {%8,%9}, {%0,%1,%2,%3};"
        : "+f"(c[0]), "+f"(c[1]), "+f"(c[2]), "+f"(c[3])
        : "r"(a[0]), "r"(a[1]), "r"(a[2]), "r"(a[3]), "r"(b0), "r"(b1));
}
__device__ __forceinline__ void ldsm4(uint32_t* r, uint32_t addr) {
    asm volatile("ldmatrix.sync.aligned.m8n8.x4.shared.b16 {%0,%1,%2,%3}, [%4];"
                 : "=r"(r[0]), "=r"(r[1]), "=r"(r[2]), "=r"(r[3]) : "r"(addr));
}

// ---------------- kernel 1: high-occupancy projections + fused SR fragment emit ----
// 64 blocks x 16 rows, 512 threads. Thread = 1 row x 4 cols.
__global__ __launch_bounds__(512, 2)
void proj3_kernel(const float* __restrict__ s,
                  const float* __restrict__ Wl, const float* __restrict__ bl,
                  const float* __restrict__ Wr, const float* __restrict__ br) {
    __shared__ float Ss[16][512];     // 32 KB: block's 16 s-rows
    __shared__ float srbuf[16 * 64];  // 4 KB: right-half results

    const int t = threadIdx.x;
    const int r0 = blockIdx.x * 16;

    // stage s rows (float4, fully coalesced)
    for (int i = t; i < 2048; i += 512) {
        int row = i >> 7, kk = (i & 127) * 4;
        *(float4*)&Ss[row][kk] = *(const float4*)(s + (size_t)(r0 + row) * IN_DIM + kk);
    }
    __syncthreads();

    const int row = t >> 5;          // 0..15 (warp id)
    const int c4 = (t & 31) * 4;     // 0..124
    const bool left = (c4 < 64);
    const float* Wp = left ? (Wl + c4) : (Wr + (c4 - 64));
    const float* bp = left ? (bl + c4) : (br + (c4 - 64));

    float a0 = bp[0], a1 = bp[1], a2 = bp[2], a3 = bp[3];
    const float* srow = Ss[row];
#pragma unroll 8
    for (int k = 0; k < IN_DIM; k++) {
        float4 wv = __ldg((const float4*)(Wp + (size_t)k * 64));
        float sv = srow[k];
        a0 = fmaf(sv, wv.x, a0);
        a1 = fmaf(sv, wv.y, a1);
        a2 = fmaf(sv, wv.z, a2);
        a3 = fmaf(sv, wv.w, a3);
    }

    if (left)
        *(float4*)&g_sl[(size_t)(r0 + row) * 64 + c4] = make_float4(a0, a1, a2, a3);
    else
        *(float4*)&srbuf[row * 64 + (c4 - 64)] = make_float4(a0, a1, a2, a3);
    __syncthreads();

    // emit fragment-layout fp16 hi/lo for this mb tile (512 items, 1/thread)
    {
        const int bb = blockIdx.x >> 5, mb = blockIdx.x & 31;
        uint32_t* oh = g_srfh + (((size_t)bb * 32 + mb) * 32) * 16;
        uint32_t* ol = g_srfl + (((size_t)bb * 32 + mb) * 32) * 16;
        int idx = t;                     // = l*16 + r
        int l = idx >> 4, r = idx & 15;
        int tt = r >> 2, e = r & 3;
        int lrow = (l >> 2) + (e & 1) * 8;
        int c = (l & 3) * 2 + 16 * tt + (e & 2) * 4;
        uint2 sp = split2h(srbuf[lrow * 64 + c], srbuf[lrow * 64 + c + 1]);
        oh[idx] = sp.x;
        ol[idx] = sp.y;
    }
}

// ---------------- kernel 2: positional table + fused weight transposes ----------------
__global__ void pos_kernel(const float* __restrict__ emb,
                           const float* __restrict__ W1,
                           const float* __restrict__ b1,
                           const float* __restrict__ W2) {
    __shared__ float erow[EMB];
    const int dist = blockIdx.x;
    const int h = threadIdx.x;

    // fused prep: blocks 0..63 also transpose W1-top / W2 (8192 items total)
    if (blockIdx.x < 64) {
        int i = blockIdx.x * 128 + h;
        {
            int j = i >> 6, d = i & 63;
            g_W1Tf[i] = W1[d * HID + j];
        }
        {
            int o = i & 63, jj = i >> 6;
            g_W2Th[o * HID + jj] = __half_as_ushort(__float2half_rn(W2[jj * EMB + o]));
        }
    }

    if (h < EMB) erow[h] = emb[dist * EMB + h];
    __syncthreads();
    float acc = b1[h];
#pragma unroll
    for (int d = 0; d < EMB; d++)
        acc = fmaf(erow[d], W1[(EMB + d) * HID + h], acc);
    g_P[dist * HID + h] = acc;
}

// ---------------- main kernel: folded-B1, coalesced A-frag LDG, 2 CTAs ----------------
// smem: sl 256B | b2 256B | W1' [128 j][72 fp16] 144B-stride | W2 [64 o][136] 272B-stride
#define OFF_SL   0
#define OFF_B2S  256
#define OFF_W1   512
#define OFF_W2   (OFF_W1 + 18432)
#define SMEM_MAIN (OFF_W2 + 17408)   // 36352 bytes

__global__ __launch_bounds__(256, 2)
void pair_mma_kernel(const float* __restrict__ b2, float* __restrict__ out) {
    extern __shared__ char sm[];
    const uint32_t smb = smem_u32_of(sm);
    const int tid = threadIdx.x;
    const int w = tid >> 5, l = tid & 31;
    const int n = blockIdx.x, b = blockIdx.y;

    float* sl = (float*)(sm + OFF_SL);
    float* b2s = (float*)(sm + OFF_B2S);
    if (tid < 64) {
        sl[tid] = g_sl[((size_t)b * N_ + n) * EMB + tid];
        b2s[tid] = b2[tid];
    }
    for (int i = tid; i < 2048; i += 256) {
        int o = i >> 5, j8 = (i & 31) * 8;
        *(uint2*)(sm + OFF_W2 + o * 272 + j8) = ((const uint2*)g_W2Th)[i];
    }
    __syncthreads();   // sl ready for the fold below

    // build B1'[j][d] = fp16(W1^T[j][d] * sl[d]) into smem (ldsm layout)
    for (int g = tid; g < 2048; g += 256) {
        int j = g >> 4, d0 = (g & 15) * 4;
        float4 wv = *(const float4*)(g_W1Tf + j * 64 + d0);
        float4 sv = *(const float4*)(sl + d0);
        __half2 h0 = __floats2half2_rn(wv.x * sv.x, wv.y * sv.y);
        __half2 h1 = __floats2half2_rn(wv.z * sv.z, wv.w * sv.w);
        *(uint2*)(sm + OFF_W1 + j * 144 + d0 * 2) =
            make_uint2(*reinterpret_cast<uint32_t*>(&h0),
                       *reinterpret_cast<uint32_t*>(&h1));
    }
    __syncthreads();   // smem read-only below: mt loop has NO barriers

    // ---- per-thread ldmatrix base addresses for B operands (x4 forms) ----
    const uint32_t preB1 = smb + OFF_W1 +
        ((l & 7) + ((l >> 4) << 3)) * 144 + ((l >> 3) & 1) * 16;
    const uint32_t preB2 = smb + OFF_W2 +
        ((l & 7) + ((l >> 4) << 3)) * 272 + ((l >> 3) & 1) * 16;

    const int fc0 = (l & 3) * 2;
    const int fr0 = 16 * w + (l >> 2);

    for (int mt = 0; mt < 4; mt++) {
        const int m_t = mt * 128 + fr0;
        const int mb = mt * 8 + w;

        // ---- A fragments: pure coalesced LDG.128 (pre-split in proj3) ----
        uint4 hv[4], lv[4];
        {
            const uint4* hp = (const uint4*)(g_srfh +
                ((((size_t)b * 32 + mb) * 32 + l) * 16));
            const uint4* lp = (const uint4*)(g_srfl +
                ((((size_t)b * 32 + mb) * 32 + l) * 16));
#pragma unroll
            for (int t = 0; t < 4; t++) { hv[t] = hp[t]; lv[t] = lp[t]; }
        }

        // ---- GEMM1: H[16,128] per warp = SR @ B1'^T, 2-term fp16 ----
        float D1[16][4];
#pragma unroll
        for (int q = 0; q < 16; q++)
#pragma unroll
            for (int e = 0; e < 4; e++) D1[q][e] = 0.0f;

#pragma unroll
        for (int t = 0; t < 4; t++) {
#pragma unroll
            for (int qq = 0; qq < 8; qq++) {
                uint32_t bh[4];
                ldsm4(bh, preB1 + qq * 2304 + t * 32);
                mma16816(D1[2 * qq],     (const uint32_t*)&hv[t], bh[0], bh[1]);
                mma16816(D1[2 * qq + 1], (const uint32_t*)&hv[t], bh[2], bh[3]);
                mma16816(D1[2 * qq],     (const uint32_t*)&lv[t], bh[0], bh[1]);
                mma16816(D1[2 * qq + 1], (const uint32_t*)&lv[t], bh[2], bh[3]);
            }
        }

        // ---- relu(H + P[dist]) in registers ----
        {
            const float* P0 = g_P + (size_t)(n - m_t + 512) * HID;
            const float* P1 = P0 - 8 * HID;   // row m_t+8
#pragma unroll
            for (int q = 0; q < 16; q++) {
                const int jc = 8 * q + fc0;
                float2 p0 = __ldg((const float2*)(P0 + jc));
                float2 p1 = __ldg((const float2*)(P1 + jc));
                D1[q][0] = fmaxf(D1[q][0] + p0.x, 0.0f);
                D1[q][1] = fmaxf(D1[q][1] + p0.y, 0.0f);
                D1[q][2] = fmaxf(D1[q][2] + p1.x, 0.0f);
                D1[q][3] = fmaxf(D1[q][3] + p1.y, 0.0f);
            }
        }

        // ---- GEMM2: out = Hrelu @ W2, 2-term fp16 (A from registers) ----
        float D2[8][4];
#pragma unroll
        for (int q = 0; q < 8; q++)
#pragma unroll
            for (int e = 0; e < 4; e++) D2[q][e] = 0.0f;

#pragma unroll
        for (int t2 = 0; t2 < 8; t2++) {
            uint32_t ah2[4], al2[4];
            {
                uint2 s0 = split2h(D1[2 * t2][0],     D1[2 * t2][1]);
                uint2 s1 = split2h(D1[2 * t2][2],     D1[2 * t2][3]);
                uint2 s2 = split2h(D1[2 * t2 + 1][0], D1[2 * t2 + 1][1]);
                uint2 s3 = split2h(D1[2 * t2 + 1][2], D1[2 * t2 + 1][3]);
                ah2[0] = s0.x; al2[0] = s0.y;
                ah2[1] = s1.x; al2[1] = s1.y;
                ah2[2] = s2.x; al2[2] = s2.y;
                ah2[3] = s3.x; al2[3] = s3.y;
            }
#pragma unroll
            for (int qq = 0; qq < 4; qq++) {
                uint32_t bh[4];
                ldsm4(bh, preB2 + qq * 4352 + t2 * 32);
                mma16816(D2[2 * qq],     ah2, bh[0], bh[1]);
                mma16816(D2[2 * qq + 1], ah2, bh[2], bh[3]);
                mma16816(D2[2 * qq],     al2, bh[0], bh[1]);
                mma16816(D2[2 * qq + 1], al2, bh[2], bh[3]);
            }
        }

        // ---- epilogue: + b2 (from smem), store fp32 ----
        {
            float* ob = out + (((size_t)b * N_ + n) * N_ + m_t) * EMB;
#pragma unroll
            for (int q = 0; q < 8; q++) {
                const int oc = 8 * q + fc0;
                float2 bb = *(const float2*)(b2s + oc);
                *(float2*)(ob + oc) =
                    make_float2(D2[q][0] + bb.x, D2[q][1] + bb.y);
                *(float2*)(ob + 8 * EMB + oc) =
                    make_float2(D2[q][2] + bb.x, D2[q][3] + bb.y);
            }
        }
    }
}

// ---------------- launch ----------------
extern "C" void kernel_launch(void* const* d_in, const int* in_sizes, int n_in,
                              void* d_out, int out_size) {
    const float* s       = (const float*)d_in[0];
    const float* W_left  = (const float*)d_in[1];
    const float* b_left  = (const float*)d_in[2];
    const float* W_right = (const float*)d_in[3];
    const float* b_right = (const float*)d_in[4];
    const float* emb     = (const float*)d_in[5];
    const float* W1      = (const float*)d_in[6];
    const float* b1      = (const float*)d_in[7];
    const float* W2      = (const float*)d_in[8];
    const float* b2      = (const float*)d_in[9];
    float* out = (float*)d_out;

    cudaFuncSetAttribute(pair_mma_kernel,
                         cudaFuncAttributeMaxDynamicSharedMemorySize, SMEM_MAIN);

    proj3_kernel<<<64, 512>>>(s, W_left, b_left, W_right, b_right);
    pos_kernel<<<NPOS, 128>>>(emb, W1, b1, W2);
    pair_mma_kernel<<<dim3(N_, B_), 256, SMEM_MAIN>>>(b2, out);
}

// round 15
// speedup vs baseline: 1.4531x; 1.1258x over previous
#include <cuda_runtime.h>
#include <cuda_fp16.h>
#include <stdint.h>

#define B_ 2
#define N_ 512
#define IN_DIM 512
#define EMB 64
#define HID 128
#define NPOS 1025

// ---------------- device scratch (no cudaMalloc allowed) ----------------
__device__ float g_sl[B_ * N_ * EMB];
__device__ float g_P[NPOS * HID];
__device__ float g_W1Tf[HID * EMB];            // fp32 W1_top^T [j][d]
__device__ unsigned short g_W2Th[EMB * HID];   // fp16(W2^T) [o][j]
// SR pre-split into mma fragment layout: [b][mb(32)][lane(32)][16 words]
__device__ uint32_t g_srfh[B_ * 32 * 32 * 16];
__device__ uint32_t g_srfl[B_ * 32 * 32 * 16];

// ---------------- helpers ----------------
__device__ __forceinline__ uint32_t smem_u32_of(const void* p) {
    uint32_t a;
    asm("{ .reg .u64 t; cvta.to.shared.u64 t, %1; cvt.u32.u64 %0, t; }"
        : "=r"(a) : "l"(p));
    return a;
}
// fp16 hi/lo split of a float pair -> (hi_half2, lo_half2)
__device__ __forceinline__ uint2 split2h(float e0, float e1) {
    __half2 h = __floats2half2_rn(e0, e1);
    float f0 = __half2float(__low2half(h));
    float f1 = __half2float(__high2half(h));
    __half2 lo = __floats2half2_rn(e0 - f0, e1 - f1);
    return make_uint2(*reinterpret_cast<uint32_t*>(&h),
                      *reinterpret_cast<uint32_t*>(&lo));
}
__device__ __forceinline__ void mma16816(float* c, const uint32_t* a,
                                         uint32_t b0, uint32_t b1) {
    asm volatile(
        "mma.sync.aligned.m16n8k16.row.col.f32.f16.f16.f32 "
        "{%0,%1,%2,%3}, {%4,%5,%6,%7}, {%8,%9}, {%0,%1,%2,%3};"
        : "+f"(c[0]), "+f"(c[1]), "+f"(c[2]), "+f"(c[3])
        : "r"(a[0]), "r"(a[1]), "r"(a[2]), "r"(a[3]), "r"(b0), "r"(b1));
}
__device__ __forceinline__ void ldsm4(uint32_t* r, uint32_t addr) {
    asm volatile("ldmatrix.sync.aligned.m8n8.x4.shared.b16 {%0,%1,%2,%3}, [%4];"
                 : "=r"(r[0]), "=r"(r[1]), "=r"(r[2]), "=r"(r[3]) : "r"(addr));
}

// ---------------- fused prologue: proj (blocks 0..127) + pos/prep (blocks 128..384) ----
// proj: 8 rows/block, 512 threads = row(8) x col4(32) x khalf(2); k-split reduce in smem.
// pos: 4 dists/block; first 16 pos blocks also do the weight transposes.
__global__ __launch_bounds__(512, 2)
void prologue_kernel(const float* __restrict__ s,
                     const float* __restrict__ Wl, const float* __restrict__ bl,
                     const float* __restrict__ Wr, const float* __restrict__ br,
                     const float* __restrict__ emb,
                     const float* __restrict__ W1, const float* __restrict__ b1,
                     const float* __restrict__ W2) {
    const int t = threadIdx.x;
    const int bid = blockIdx.x;

    if (bid < 128) {
        // ================= proj part =================
        __shared__ float Ss[8][512];       // 16 KB
        __shared__ float red[256 * 4];     // 4 KB k-split partials
        __shared__ float srbuf[8 * 64];    // 2 KB right-half results

        const int r0 = bid * 8;

        for (int i = t; i < 1024; i += 512) {
            int row = i >> 7, kk = (i & 127) * 4;
            *(float4*)&Ss[row][kk] = *(const float4*)(s + (size_t)(r0 + row) * IN_DIM + kk);
        }
        __syncthreads();

        const int kh = t >> 8;            // warps 0-7: kh=0, warps 8-15: kh=1
        const int rt = t & 255;
        const int row = rt >> 5;
        const int c4 = (rt & 31) * 4;
        const bool left = (c4 < 64);
        const float* Wp = left ? (Wl + c4) : (Wr + (c4 - 64));
        const float* bp = left ? (bl + c4) : (br + (c4 - 64));

        float a0, a1, a2, a3;
        if (kh == 0) { a0 = bp[0]; a1 = bp[1]; a2 = bp[2]; a3 = bp[3]; }
        else         { a0 = a1 = a2 = a3 = 0.0f; }

        const float* srow = Ss[row];
        const int k0 = kh * 256;
#pragma unroll 8
        for (int k = k0; k < k0 + 256; k++) {
            float4 wv = __ldg((const float4*)(Wp + (size_t)k * 64));
            float sv = srow[k];
            a0 = fmaf(sv, wv.x, a0);
            a1 = fmaf(sv, wv.y, a1);
            a2 = fmaf(sv, wv.z, a2);
            a3 = fmaf(sv, wv.w, a3);
        }

        if (kh == 1)
            *(float4*)&red[rt * 4] = make_float4(a0, a1, a2, a3);
        __syncthreads();
        if (kh == 0) {
            float4 pv = *(const float4*)&red[rt * 4];
            a0 += pv.x; a1 += pv.y; a2 += pv.z; a3 += pv.w;
            if (left)
                *(float4*)&g_sl[(size_t)(r0 + row) * 64 + c4] =
                    make_float4(a0, a1, a2, a3);
            else
                *(float4*)&srbuf[row * 64 + (c4 - 64)] =
                    make_float4(a0, a1, a2, a3);
        }
        __syncthreads();

        // emit fragment-layout fp16 hi/lo: this block covers half an mb tile
        if (t < 256) {
            const int bb = bid >> 6, mb = (bid >> 1) & 31, half = bid & 1;
            uint32_t* oh = g_srfh + (((size_t)bb * 32 + mb) * 32) * 16;
            uint32_t* ol = g_srfl + (((size_t)bb * 32 + mb) * 32) * 16;
            int l = t >> 3, rr = t & 7;
            int r = rr * 2 + half;              // words with (r&1)==half
            int tt = r >> 2, e = r & 3;
            int lrow = l >> 2;                  // local row 0..7
            int c = (l & 3) * 2 + 16 * tt + (e & 2) * 4;
            int idx = l * 16 + r;
            uint2 sp = split2h(srbuf[lrow * 64 + c], srbuf[lrow * 64 + c + 1]);
            oh[idx] = sp.x;
            ol[idx] = sp.y;
        }
    } else {
        // ================= pos part (+ fused weight transposes) =================
        __shared__ float erow[4][EMB];
        const int pb = bid - 128;           // 0..256
        const int h = t & 127;
        const int dl = t >> 7;              // 0..3
        const int dist = pb * 4 + dl;

        if (pb < 16) {                      // weight transposes: 16 blocks x 512 = 8192
            int i = pb * 512 + t;
            {
                int j = i >> 6, d = i & 63;
                g_W1Tf[i] = W1[d * HID + j];
            }
            {
                int o = i & 63, jj = i >> 6;
                g_W2Th[o * HID + jj] = __half_as_ushort(__float2half_rn(W2[jj * EMB + o]));
            }
        }

        if (dist < NPOS && h < EMB)
            erow[dl][h] = emb[dist * EMB + h];
        __syncthreads();

        if (dist < NPOS) {
            float acc = b1[h];
#pragma unroll
            for (int d = 0; d < EMB; d++)
                acc = fmaf(erow[dl][d], W1[(EMB + d) * HID + h], acc);
            g_P[dist * HID + h] = acc;
        }
    }
}

// ---------------- main kernel: folded-B1, coalesced A-frag LDG, 2 CTAs ----------------
// smem: sl 256B | b2 256B | W1' [128 j][72 fp16] 144B-stride | W2 [64 o][136] 272B-stride
#define OFF_SL   0
#define OFF_B2S  256
#define OFF_W1   512
#define OFF_W2   (OFF_W1 + 18432)
#define SMEM_MAIN (OFF_W2 + 17408)   // 36352 bytes

__global__ __launch_bounds__(256, 2)
void pair_mma_kernel(const float* __restrict__ b2, float* __restrict__ out) {
    extern __shared__ char sm[];
    const uint32_t smb = smem_u32_of(sm);
    const int tid = threadIdx.x;
    const int w = tid >> 5, l = tid & 31;
    const int n = blockIdx.x, b = blockIdx.y;

    float* sl = (float*)(sm + OFF_SL);
    float* b2s = (float*)(sm + OFF_B2S);
    if (tid < 64) {
        sl[tid] = g_sl[((size_t)b * N_ + n) * EMB + tid];
        b2s[tid] = b2[tid];
    }
    for (int i = tid; i < 2048; i += 256) {
        int o = i >> 5, j8 = (i & 31) * 8;
        *(uint2*)(sm + OFF_W2 + o * 272 + j8) = ((const uint2*)g_W2Th)[i];
    }
    __syncthreads();   // sl ready for the fold below

    // build B1'[j][d] = fp16(W1^T[j][d] * sl[d]) into smem (ldsm layout)
    for (int g = tid; g < 2048; g += 256) {
        int j = g >> 4, d0 = (g & 15) * 4;
        float4 wv = *(const float4*)(g_W1Tf + j * 64 + d0);
        float4 sv = *(const float4*)(sl + d0);
        __half2 h0 = __floats2half2_rn(wv.x * sv.x, wv.y * sv.y);
        __half2 h1 = __floats2half2_rn(wv.z * sv.z, wv.w * sv.w);
        *(uint2*)(sm + OFF_W1 + j * 144 + d0 * 2) =
            make_uint2(*reinterpret_cast<uint32_t*>(&h0),
                       *reinterpret_cast<uint32_t*>(&h1));
    }
    __syncthreads();   // smem read-only below: mt loop has NO barriers

    // ---- per-thread ldmatrix base addresses for B operands (x4 forms) ----
    const uint32_t preB1 = smb + OFF_W1 +
        ((l & 7) + ((l >> 4) << 3)) * 144 + ((l >> 3) & 1) * 16;
    const uint32_t preB2 = smb + OFF_W2 +
        ((l & 7) + ((l >> 4) << 3)) * 272 + ((l >> 3) & 1) * 16;

    const int fc0 = (l & 3) * 2;
    const int fr0 = 16 * w + (l >> 2);

    for (int mt = 0; mt < 4; mt++) {
        const int m_t = mt * 128 + fr0;
        const int mb = mt * 8 + w;

        // ---- A fragments: pure coalesced LDG.128 (pre-split in prologue) ----
        uint4 hv[4], lv[4];
        {
            const uint4* hp = (const uint4*)(g_srfh +
                ((((size_t)b * 32 + mb) * 32 + l) * 16));
            const uint4* lp = (const uint4*)(g_srfl +
                ((((size_t)b * 32 + mb) * 32 + l) * 16));
#pragma unroll
            for (int t = 0; t < 4; t++) { hv[t] = hp[t]; lv[t] = lp[t]; }
        }

        // ---- GEMM1: H[16,128] per warp = SR @ B1'^T, 2-term fp16 ----
        float D1[16][4];
#pragma unroll
        for (int q = 0; q < 16; q++)
#pragma unroll
            for (int e = 0; e < 4; e++) D1[q][e] = 0.0f;

#pragma unroll
        for (int t = 0; t < 4; t++) {
#pragma unroll
            for (int qq = 0; qq < 8; qq++) {
                uint32_t bh[4];
                ldsm4(bh, preB1 + qq * 2304 + t * 32);
                mma16816(D1[2 * qq],     (const uint32_t*)&hv[t], bh[0], bh[1]);
                mma16816(D1[2 * qq + 1], (const uint32_t*)&hv[t], bh[2], bh[3]);
                mma16816(D1[2 * qq],     (const uint32_t*)&lv[t], bh[0], bh[1]);
                mma16816(D1[2 * qq + 1], (const uint32_t*)&lv[t], bh[2], bh[3]);
            }
        }

        // ---- relu(H + P[dist]) in registers ----
        {
            const float* P0 = g_P + (size_t)(n - m_t + 512) * HID;
            const float* P1 = P0 - 8 * HID;   // row m_t+8
#pragma unroll
            for (int q = 0; q < 16; q++) {
                const int jc = 8 * q + fc0;
                float2 p0 = __ldg((const float2*)(P0 + jc));
                float2 p1 = __ldg((const float2*)(P1 + jc));
                D1[q][0] = fmaxf(D1[q][0] + p0.x, 0.0f);
                D1[q][1] = fmaxf(D1[q][1] + p0.y, 0.0f);
                D1[q][2] = fmaxf(D1[q][2] + p1.x, 0.0f);
                D1[q][3] = fmaxf(D1[q][3] + p1.y, 0.0f);
            }
        }

        // ---- GEMM2: out = Hrelu @ W2, 2-term fp16 (A from registers) ----
        float D2[8][4];
#pragma unroll
        for (int q = 0; q < 8; q++)
#pragma unroll
            for (int e = 0; e < 4; e++) D2[q][e] = 0.0f;

#pragma unroll
        for (int t2 = 0; t2 < 8; t2++) {
            uint32_t ah2[4], al2[4];
            {
                uint2 s0 = split2h(D1[2 * t2][0],     D1[2 * t2][1]);
                uint2 s1 = split2h(D1[2 * t2][2],     D1[2 * t2][3]);
                uint2 s2 = split2h(D1[2 * t2 + 1][0], D1[2 * t2 + 1][1]);
                uint2 s3 = split2h(D1[2 * t2 + 1][2], D1[2 * t2 + 1][3]);
                ah2[0] = s0.x; al2[0] = s0.y;
                ah2[1] = s1.x; al2[1] = s1.y;
                ah2[2] = s2.x; al2[2] = s2.y;
                ah2[3] = s3.x; al2[3] = s3.y;
            }
#pragma unroll
            for (int qq = 0; qq < 4; qq++) {
                uint32_t bh[4];
                ldsm4(bh, preB2 + qq * 4352 + t2 * 32);
                mma16816(D2[2 * qq],     ah2, bh[0], bh[1]);
                mma16816(D2[2 * qq + 1], ah2, bh[2], bh[3]);
                mma16816(D2[2 * qq],     al2, bh[0], bh[1]);
                mma16816(D2[2 * qq + 1], al2, bh[2], bh[3]);
            }
        }

        // ---- epilogue: + b2 (from smem), store fp32 ----
        {
            float* ob = out + (((size_t)b * N_ + n) * N_ + m_t) * EMB;
#pragma unroll
            for (int q = 0; q < 8; q++) {
                const int oc = 8 * q + fc0;
                float2 bb = *(const float2*)(b2s + oc);
                *(float2*)(ob + oc) =
                    make_float2(D2[q][0] + bb.x, D2[q][1] + bb.y);
                *(float2*)(ob + 8 * EMB + oc) =
                    make_float2(D2[q][2] + bb.x, D2[q][3] + bb.y);
            }
        }
    }
}

// ---------------- launch ----------------
extern "C" void kernel_launch(void* const* d_in, const int* in_sizes, int n_in,
                              void* d_out, int out_size) {
    const float* s       = (const float*)d_in[0];
    const float* W_left  = (const float*)d_in[1];
    const float* b_left  = (const float*)d_in[2];
    const float* W_right = (const float*)d_in[3];
    const float* b_right = (const float*)d_in[4];
    const float* emb     = (const float*)d_in[5];
    const float* W1      = (const float*)d_in[6];
    const float* b1      = (const float*)d_in[7];
    const float* W2      = (const float*)d_in[8];
    const float* b2      = (const float*)d_in[9];
    float* out = (float*)d_out;

    cudaFuncSetAttribute(pair_mma_kernel,
                         cudaFuncAttributeMaxDynamicSharedMemorySize, SMEM_MAIN);

    prologue_kernel<<<128 + 257, 512>>>(s, W_left, b_left, W_right, b_right,
                                        emb, W1, b1, W2);
    pair_mma_kernel<<<dim3(N_, B_), 256, SMEM_MAIN>>>(b2, out);
}

// round 16
// speedup vs baseline: 1.5938x; 1.0968x over previous
#include <cuda_runtime.h>
#include <cuda_fp16.h>
#include <stdint.h>

#define B_ 2
#define N_ 512
#define IN_DIM 512
#define EMB 64
#define HID 128
#define NPOS 1025

// ---------------- device scratch (no cudaMalloc allowed) ----------------
__device__ float g_sl[B_ * N_ * EMB];
__device__ float g_P[NPOS * HID];
__device__ float g_W1Tf[HID * EMB];            // fp32 W1_top^T [j][d]
__device__ unsigned short g_W2Th[EMB * HID];   // fp16(W2^T) [o][j]
// SR pre-split, fragment layout: [b][mb(32)][t(4)][lane(32)][4 words] (lane-contiguous)
__device__ uint32_t g_srfh[B_ * 32 * 512];
__device__ uint32_t g_srfl[B_ * 32 * 512];

// ---------------- helpers ----------------
__device__ __forceinline__ uint32_t smem_u32_of(const void* p) {
    uint32_t a;
    asm("{ .reg .u64 t; cvta.to.shared.u64 t, %1; cvt.u32.u64 %0, t; }"
        : "=r"(a) : "l"(p));
    return a;
}
// fp16 hi/lo split of a float pair -> (hi_half2, lo_half2)
__device__ __forceinline__ uint2 split2h(float e0, float e1) {
    __half2 h = __floats2half2_rn(e0, e1);
    float f0 = __half2float(__low2half(h));
    float f1 = __half2float(__high2half(h));
    __half2 lo = __floats2half2_rn(e0 - f0, e1 - f1);
    return make_uint2(*reinterpret_cast<uint32_t*>(&h),
                      *reinterpret_cast<uint32_t*>(&lo));
}
__device__ __forceinline__ uint32_t pack2h(float e0, float e1) {
    __half2 h = __floats2half2_rn(e0, e1);
    return *reinterpret_cast<uint32_t*>(&h);
}
__device__ __forceinline__ void mma16816(float* c, const uint32_t* a,
                                         uint32_t b0, uint32_t b1) {
    asm volatile(
        "mma.sync.aligned.m16n8k16.row.col.f32.f16.f16.f32 "
        "{%0,%1,%2,%3}, {%4,%5,%6,%7}, {%8,%9}, {%0,%1,%2,%3};"
        : "+f"(c[0]), "+f"(c[1]), "+f"(c[2]), "+f"(c[3])
        : "r"(a[0]), "r"(a[1]), "r"(a[2]), "r"(a[3]), "r"(b0), "r"(b1));
}
__device__ __forceinline__ void ldsm4(uint32_t* r, uint32_t addr) {
    asm volatile("ldmatrix.sync.aligned.m8n8.x4.shared.b16 {%0,%1,%2,%3}, [%4];"
                 : "=r"(r[0]), "=r"(r[1]), "=r"(r[2]), "=r"(r[3]) : "r"(addr));
}

// ---------------- fused prologue: proj (blocks 0..127) + pos/prep (blocks 128..384) ----
__global__ __launch_bounds__(512, 2)
void prologue_kernel(const float* __restrict__ s,
                     const float* __restrict__ Wl, const float* __restrict__ bl,
                     const float* __restrict__ Wr, const float* __restrict__ br,
                     const float* __restrict__ emb,
                     const float* __restrict__ W1, const float* __restrict__ b1,
                     const float* __restrict__ W2) {
    const int t = threadIdx.x;
    const int bid = blockIdx.x;

    if (bid < 128) {
        // ================= proj part =================
        __shared__ float Ss[8][512];       // 16 KB
        __shared__ float red[256 * 4];     // 4 KB k-split partials
        __shared__ float srbuf[8 * 64];    // 2 KB right-half results

        const int r0 = bid * 8;

        for (int i = t; i < 1024; i += 512) {
            int row = i >> 7, kk = (i & 127) * 4;
            *(float4*)&Ss[row][kk] = *(const float4*)(s + (size_t)(r0 + row) * IN_DIM + kk);
        }
        __syncthreads();

        const int kh = t >> 8;
        const int rt = t & 255;
        const int row = rt >> 5;
        const int c4 = (rt & 31) * 4;
        const bool left = (c4 < 64);
        const float* Wp = left ? (Wl + c4) : (Wr + (c4 - 64));
        const float* bp = left ? (bl + c4) : (br + (c4 - 64));

        float a0, a1, a2, a3;
        if (kh == 0) { a0 = bp[0]; a1 = bp[1]; a2 = bp[2]; a3 = bp[3]; }
        else         { a0 = a1 = a2 = a3 = 0.0f; }

        const float* srow = Ss[row];
        const int k0 = kh * 256;
#pragma unroll 8
        for (int k = k0; k < k0 + 256; k++) {
            float4 wv = __ldg((const float4*)(Wp + (size_t)k * 64));
            float sv = srow[k];
            a0 = fmaf(sv, wv.x, a0);
            a1 = fmaf(sv, wv.y, a1);
            a2 = fmaf(sv, wv.z, a2);
            a3 = fmaf(sv, wv.w, a3);
        }

        if (kh == 1)
            *(float4*)&red[rt * 4] = make_float4(a0, a1, a2, a3);
        __syncthreads();
        if (kh == 0) {
            float4 pv = *(const float4*)&red[rt * 4];
            a0 += pv.x; a1 += pv.y; a2 += pv.z; a3 += pv.w;
            if (left)
                *(float4*)&g_sl[(size_t)(r0 + row) * 64 + c4] =
                    make_float4(a0, a1, a2, a3);
            else
                *(float4*)&srbuf[row * 64 + (c4 - 64)] =
                    make_float4(a0, a1, a2, a3);
        }
        __syncthreads();

        // emit fragment-layout fp16 hi/lo, lane-contiguous packing
        if (t < 256) {
            const int bb = bid >> 6, mb = (bid >> 1) & 31, half = bid & 1;
            uint32_t* oh = g_srfh + ((size_t)bb * 32 + mb) * 512;
            uint32_t* ol = g_srfl + ((size_t)bb * 32 + mb) * 512;
            int l = t >> 3, rr = t & 7;
            int r = rr * 2 + half;              // words with (r&1)==half
            int tt = r >> 2, e = r & 3;
            int lrow = l >> 2;                  // local row 0..7
            int c = (l & 3) * 2 + 16 * tt + (e & 2) * 4;
            int idx = tt * 128 + l * 4 + e;     // NEW lane-contiguous layout
            uint2 sp = split2h(srbuf[lrow * 64 + c], srbuf[lrow * 64 + c + 1]);
            oh[idx] = sp.x;
            ol[idx] = sp.y;
        }
    } else {
        // ================= pos part (+ fused weight transposes) =================
        __shared__ float erow[4][EMB];
        const int pb = bid - 128;           // 0..256
        const int h = t & 127;
        const int dl = t >> 7;              // 0..3
        const int dist = pb * 4 + dl;

        if (pb < 16) {                      // weight transposes: 16 blocks x 512 = 8192
            int i = pb * 512 + t;
            {
                int j = i >> 6, d = i & 63;
                g_W1Tf[i] = W1[d * HID + j];
            }
            {
                int o = i & 63, jj = i >> 6;
                g_W2Th[o * HID + jj] = __half_as_ushort(__float2half_rn(W2[jj * EMB + o]));
            }
        }

        if (dist < NPOS && h < EMB)
            erow[dl][h] = emb[dist * EMB + h];
        __syncthreads();

        if (dist < NPOS) {
            float acc = b1[h];
#pragma unroll
            for (int d = 0; d < EMB; d++)
                acc = fmaf(erow[dl][d], W1[(EMB + d) * HID + h], acc);
            g_P[dist * HID + h] = acc;
        }
    }
}

// ---------------- main kernel: folded-B1, packed A-frag LDG, 2 CTAs ----------------
// smem: sl 256B | b2 256B | W1' [128 j][72 fp16] 144B-stride | W2 [64 o][136] 272B-stride
#define OFF_SL   0
#define OFF_B2S  256
#define OFF_W1   512
#define OFF_W2   (OFF_W1 + 18432)
#define SMEM_MAIN (OFF_W2 + 17408)   // 36352 bytes

__global__ __launch_bounds__(256, 2)
void pair_mma_kernel(const float* __restrict__ b2, float* __restrict__ out) {
    extern __shared__ char sm[];
    const uint32_t smb = smem_u32_of(sm);
    const int tid = threadIdx.x;
    const int w = tid >> 5, l = tid & 31;
    const int n = blockIdx.x, b = blockIdx.y;

    float* sl = (float*)(sm + OFF_SL);
    float* b2s = (float*)(sm + OFF_B2S);
    if (tid < 64) {
        sl[tid] = g_sl[((size_t)b * N_ + n) * EMB + tid];
        b2s[tid] = b2[tid];
    }
    for (int i = tid; i < 2048; i += 256) {
        int o = i >> 5, j8 = (i & 31) * 8;
        *(uint2*)(sm + OFF_W2 + o * 272 + j8) = ((const uint2*)g_W2Th)[i];
    }
    __syncthreads();   // sl ready for the fold below

    // build B1'[j][d] = fp16(W1^T[j][d] * sl[d]) into smem (ldsm layout)
    for (int g = tid; g < 2048; g += 256) {
        int j = g >> 4, d0 = (g & 15) * 4;
        float4 wv = *(const float4*)(g_W1Tf + j * 64 + d0);
        float4 sv = *(const float4*)(sl + d0);
        __half2 h0 = __floats2half2_rn(wv.x * sv.x, wv.y * sv.y);
        __half2 h1 = __floats2half2_rn(wv.z * sv.z, wv.w * sv.w);
        *(uint2*)(sm + OFF_W1 + j * 144 + d0 * 2) =
            make_uint2(*reinterpret_cast<uint32_t*>(&h0),
                       *reinterpret_cast<uint32_t*>(&h1));
    }
    __syncthreads();   // smem read-only below: mt loop has NO barriers

    // ---- per-thread ldmatrix base addresses for B operands (x4 forms) ----
    const uint32_t preB1 = smb + OFF_W1 +
        ((l & 7) + ((l >> 4) << 3)) * 144 + ((l >> 3) & 1) * 16;
    const uint32_t preB2 = smb + OFF_W2 +
        ((l & 7) + ((l >> 4) << 3)) * 272 + ((l >> 3) & 1) * 16;

    const int fc0 = (l & 3) * 2;
    const int fr0 = 16 * w + (l >> 2);

    for (int mt = 0; mt < 4; mt++) {
        const int m_t = mt * 128 + fr0;
        const int mb = mt * 8 + w;

        // ---- A fragments: sector-perfect LDG.128 (lane-contiguous layout) ----
        uint4 hv[4], lv[4];
        {
            const uint32_t* hp = g_srfh + ((size_t)b * 32 + mb) * 512;
            const uint32_t* lp = g_srfl + ((size_t)b * 32 + mb) * 512;
#pragma unroll
            for (int t = 0; t < 4; t++) {
                hv[t] = *(const uint4*)(hp + t * 128 + l * 4);
                lv[t] = *(const uint4*)(lp + t * 128 + l * 4);
            }
        }

        // ---- GEMM1: H[16,128] per warp = SR @ B1'^T, 2-term fp16 ----
        float D1[16][4];
#pragma unroll
        for (int q = 0; q < 16; q++)
#pragma unroll
            for (int e = 0; e < 4; e++) D1[q][e] = 0.0f;

#pragma unroll
        for (int t = 0; t < 4; t++) {
#pragma unroll
            for (int qq = 0; qq < 8; qq++) {
                uint32_t bh[4];
                ldsm4(bh, preB1 + qq * 2304 + t * 32);
                mma16816(D1[2 * qq],     (const uint32_t*)&hv[t], bh[0], bh[1]);
                mma16816(D1[2 * qq + 1], (const uint32_t*)&hv[t], bh[2], bh[3]);
                mma16816(D1[2 * qq],     (const uint32_t*)&lv[t], bh[0], bh[1]);
                mma16816(D1[2 * qq + 1], (const uint32_t*)&lv[t], bh[2], bh[3]);
            }
        }

        // ---- relu(H + P[dist]) in registers ----
        {
            const float* P0 = g_P + (size_t)(n - m_t + 512) * HID;
            const float* P1 = P0 - 8 * HID;   // row m_t+8
#pragma unroll
            for (int q = 0; q < 16; q++) {
                const int jc = 8 * q + fc0;
                float2 p0 = __ldg((const float2*)(P0 + jc));
                float2 p1 = __ldg((const float2*)(P1 + jc));
                D1[q][0] = fmaxf(D1[q][0] + p0.x, 0.0f);
                D1[q][1] = fmaxf(D1[q][1] + p0.y, 0.0f);
                D1[q][2] = fmaxf(D1[q][2] + p1.x, 0.0f);
                D1[q][3] = fmaxf(D1[q][3] + p1.y, 0.0f);
            }
        }

        // ---- GEMM2: out = Hrelu @ W2, single-term fp16 A (H is non-negative) ----
        float D2[8][4];
#pragma unroll
        for (int q = 0; q < 8; q++)
#pragma unroll
            for (int e = 0; e < 4; e++) D2[q][e] = 0.0f;

#pragma unroll
        for (int t2 = 0; t2 < 8; t2++) {
            uint32_t ah2[4];
            ah2[0] = pack2h(D1[2 * t2][0],     D1[2 * t2][1]);
            ah2[1] = pack2h(D1[2 * t2][2],     D1[2 * t2][3]);
            ah2[2] = pack2h(D1[2 * t2 + 1][0], D1[2 * t2 + 1][1]);
            ah2[3] = pack2h(D1[2 * t2 + 1][2], D1[2 * t2 + 1][3]);
#pragma unroll
            for (int qq = 0; qq < 4; qq++) {
                uint32_t bh[4];
                ldsm4(bh, preB2 + qq * 4352 + t2 * 32);
                mma16816(D2[2 * qq],     ah2, bh[0], bh[1]);
                mma16816(D2[2 * qq + 1], ah2, bh[2], bh[3]);
            }
        }

        // ---- epilogue: + b2 (from smem), store fp32 ----
        {
            float* ob = out + (((size_t)b * N_ + n) * N_ + m_t) * EMB;
#pragma unroll
            for (int q = 0; q < 8; q++) {
                const int oc = 8 * q + fc0;
                float2 bb = *(const float2*)(b2s + oc);
                *(float2*)(ob + oc) =
                    make_float2(D2[q][0] + bb.x, D2[q][1] + bb.y);
                *(float2*)(ob + 8 * EMB + oc) =
                    make_float2(D2[q][2] + bb.x, D2[q][3] + bb.y);
            }
        }
    }
}

// ---------------- launch ----------------
extern "C" void kernel_launch(void* const* d_in, const int* in_sizes, int n_in,
                              void* d_out, int out_size) {
    const float* s       = (const float*)d_in[0];
    const float* W_left  = (const float*)d_in[1];
    const float* b_left  = (const float*)d_in[2];
    const float* W_right = (const float*)d_in[3];
    const float* b_right = (const float*)d_in[4];
    const float* emb     = (const float*)d_in[5];
    const float* W1      = (const float*)d_in[6];
    const float* b1      = (const float*)d_in[7];
    const float* W2      = (const float*)d_in[8];
    const float* b2      = (const float*)d_in[9];
    float* out = (float*)d_out;

    cudaFuncSetAttribute(pair_mma_kernel,
                         cudaFuncAttributeMaxDynamicSharedMemorySize, SMEM_MAIN);

    prologue_kernel<<<128 + 257, 512>>>(s, W_left, b_left, W_right, b_right,
                                        emb, W1, b1, W2);
    pair_mma_kernel<<<dim3(N_, B_), 256, SMEM_MAIN>>>(b2, out);
}

// round 17
// speedup vs baseline: 1.7226x; 1.0808x over previous
#include <cuda_runtime.h>
#include <cuda_fp16.h>
#include <stdint.h>

#define B_ 2
#define N_ 512
#define IN_DIM 512
#define EMB 64
#define HID 128
#define NPOS 1025

// ---------------- device scratch (no cudaMalloc allowed) ----------------
__device__ float g_sl[B_ * N_ * EMB];
__device__ float g_P[NPOS * HID];
__device__ float g_W1Tf[HID * EMB];            // fp32 W1_top^T [j][d]
__device__ unsigned short g_W2Th[EMB * HID];   // fp16(W2^T) [o][j]
// SR fp16 fragment layout: [b][mb(32)][t(4)][lane(32)][4 words] (lane-contiguous)
__device__ uint32_t g_srfh[B_ * 32 * 512];

// ---------------- helpers ----------------
__device__ __forceinline__ uint32_t smem_u32_of(const void* p) {
    uint32_t a;
    asm("{ .reg .u64 t; cvta.to.shared.u64 t, %1; cvt.u32.u64 %0, t; }"
        : "=r"(a) : "l"(p));
    return a;
}
__device__ __forceinline__ uint32_t pack2h(float e0, float e1) {
    __half2 h = __floats2half2_rn(e0, e1);
    return *reinterpret_cast<uint32_t*>(&h);
}
__device__ __forceinline__ void mma16816(float* c, const uint32_t* a,
                                         uint32_t b0, uint32_t b1) {
    asm volatile(
        "mma.sync.aligned.m16n8k16.row.col.f32.f16.f16.f32 "
        "{%0,%1,%2,%3}, {%4,%5,%6,%7}, {%8,%9}, {%0,%1,%2,%3};"
        : "+f"(c[0]), "+f"(c[1]), "+f"(c[2]), "+f"(c[3])
        : "r"(a[0]), "r"(a[1]), "r"(a[2]), "r"(a[3]), "r"(b0), "r"(b1));
}
__device__ __forceinline__ void ldsm4(uint32_t* r, uint32_t addr) {
    asm volatile("ldmatrix.sync.aligned.m8n8.x4.shared.b16 {%0,%1,%2,%3}, [%4];"
                 : "=r"(r[0]), "=r"(r[1]), "=r"(r[2]), "=r"(r[3]) : "r"(addr));
}

// ---------------- fused prologue: proj (blocks 0..127) + pos/prep (blocks 128..384) ----
__global__ __launch_bounds__(512, 2)
void prologue_kernel(const float* __restrict__ s,
                     const float* __restrict__ Wl, const float* __restrict__ bl,
                     const float* __restrict__ Wr, const float* __restrict__ br,
                     const float* __restrict__ emb,
                     const float* __restrict__ W1, const float* __restrict__ b1,
                     const float* __restrict__ W2) {
    const int t = threadIdx.x;
    const int bid = blockIdx.x;

    if (bid < 128) {
        // ================= proj part =================
        __shared__ float Ss[8][512];       // 16 KB
        __shared__ float red[256 * 4];     // 4 KB k-split partials
        __shared__ float srbuf[8 * 64];    // 2 KB right-half results

        const int r0 = bid * 8;

        for (int i = t; i < 1024; i += 512) {
            int row = i >> 7, kk = (i & 127) * 4;
            *(float4*)&Ss[row][kk] = *(const float4*)(s + (size_t)(r0 + row) * IN_DIM + kk);
        }
        __syncthreads();

        const int kh = t >> 8;
        const int rt = t & 255;
        const int row = rt >> 5;
        const int c4 = (rt & 31) * 4;
        const bool left = (c4 < 64);
        const float* Wp = left ? (Wl + c4) : (Wr + (c4 - 64));
        const float* bp = left ? (bl + c4) : (br + (c4 - 64));

        float a0, a1, a2, a3;
        if (kh == 0) { a0 = bp[0]; a1 = bp[1]; a2 = bp[2]; a3 = bp[3]; }
        else         { a0 = a1 = a2 = a3 = 0.0f; }

        const float* srow = Ss[row];
        const int k0 = kh * 256;
#pragma unroll 8
        for (int k = k0; k < k0 + 256; k++) {
            float4 wv = __ldg((const float4*)(Wp + (size_t)k * 64));
            float sv = srow[k];
            a0 = fmaf(sv, wv.x, a0);
            a1 = fmaf(sv, wv.y, a1);
            a2 = fmaf(sv, wv.z, a2);
            a3 = fmaf(sv, wv.w, a3);
        }

        if (kh == 1)
            *(float4*)&red[rt * 4] = make_float4(a0, a1, a2, a3);
        __syncthreads();
        if (kh == 0) {
            float4 pv = *(const float4*)&red[rt * 4];
            a0 += pv.x; a1 += pv.y; a2 += pv.z; a3 += pv.w;
            if (left)
                *(float4*)&g_sl[(size_t)(r0 + row) * 64 + c4] =
                    make_float4(a0, a1, a2, a3);
            else
                *(float4*)&srbuf[row * 64 + (c4 - 64)] =
                    make_float4(a0, a1, a2, a3);
        }
        __syncthreads();

        // emit fragment-layout fp16 (hi only), lane-contiguous packing
        if (t < 256) {
            const int bb = bid >> 6, mb = (bid >> 1) & 31, half = bid & 1;
            uint32_t* oh = g_srfh + ((size_t)bb * 32 + mb) * 512;
            int l = t >> 3, rr = t & 7;
            int r = rr * 2 + half;              // words with (r&1)==half
            int tt = r >> 2, e = r & 3;
            int lrow = l >> 2;                  // local row 0..7
            int c = (l & 3) * 2 + 16 * tt + (e & 2) * 4;
            int idx = tt * 128 + l * 4 + e;     // lane-contiguous layout
            oh[idx] = pack2h(srbuf[lrow * 64 + c], srbuf[lrow * 64 + c + 1]);
        }
    } else {
        // ================= pos part (+ fused weight transposes) =================
        __shared__ float erow[4][EMB];
        const int pb = bid - 128;           // 0..256
        const int h = t & 127;
        const int dl = t >> 7;              // 0..3
        const int dist = pb * 4 + dl;

        if (pb < 16) {                      // weight transposes: 16 blocks x 512 = 8192
            int i = pb * 512 + t;
            {
                int j = i >> 6, d = i & 63;
                g_W1Tf[i] = W1[d * HID + j];
            }
            {
                int o = i & 63, jj = i >> 6;
                g_W2Th[o * HID + jj] = __half_as_ushort(__float2half_rn(W2[jj * EMB + o]));
            }
        }

        if (dist < NPOS && h < EMB)
            erow[dl][h] = emb[dist * EMB + h];
        __syncthreads();

        if (dist < NPOS) {
            float acc = b1[h];
#pragma unroll
            for (int d = 0; d < EMB; d++)
                acc = fmaf(erow[dl][d], W1[(EMB + d) * HID + h], acc);
            g_P[dist * HID + h] = acc;
        }
    }
}

// ---------------- main kernel: 128 threads, 4 warps x 32 rows, jh-split GEMM2 ----------------
// smem: sl 256B | b2 256B | W1' [128 j][72 fp16] 144B-stride | W2 [64 o][136] 272B-stride
#define OFF_SL   0
#define OFF_B2S  256
#define OFF_W1   512
#define OFF_W2   (OFF_W1 + 18432)
#define SMEM_MAIN (OFF_W2 + 17408)   // 36352 bytes

__global__ __launch_bounds__(128, 2)
void pair_mma_kernel(const float* __restrict__ b2, float* __restrict__ out) {
    extern __shared__ char sm[];
    const uint32_t smb = smem_u32_of(sm);
    const int tid = threadIdx.x;
    const int w = tid >> 5, l = tid & 31;   // 4 warps
    const int n = blockIdx.x, b = blockIdx.y;

    float* sl = (float*)(sm + OFF_SL);
    float* b2s = (float*)(sm + OFF_B2S);
    if (tid < 64) {
        sl[tid] = g_sl[((size_t)b * N_ + n) * EMB + tid];
        b2s[tid] = b2[tid];
    }
    for (int i = tid; i < 2048; i += 128) {
        int o = i >> 5, j8 = (i & 31) * 8;
        *(uint2*)(sm + OFF_W2 + o * 272 + j8) = ((const uint2*)g_W2Th)[i];
    }
    __syncthreads();   // sl ready for the fold below

    // build B1'[j][d] = fp16(W1^T[j][d] * sl[d]) into smem (ldsm layout)
    for (int g = tid; g < 2048; g += 128) {
        int j = g >> 4, d0 = (g & 15) * 4;
        float4 wv = *(const float4*)(g_W1Tf + j * 64 + d0);
        float4 sv = *(const float4*)(sl + d0);
        __half2 h0 = __floats2half2_rn(wv.x * sv.x, wv.y * sv.y);
        __half2 h1 = __floats2half2_rn(wv.z * sv.z, wv.w * sv.w);
        *(uint2*)(sm + OFF_W1 + j * 144 + d0 * 2) =
            make_uint2(*reinterpret_cast<uint32_t*>(&h0),
                       *reinterpret_cast<uint32_t*>(&h1));
    }
    __syncthreads();   // smem read-only below: mt loop has NO barriers

    // ---- per-thread ldmatrix base addresses for B operands (x4 forms) ----
    const uint32_t preB1 = smb + OFF_W1 +
        ((l & 7) + ((l >> 4) << 3)) * 144 + ((l >> 3) & 1) * 16;
    const uint32_t preB2 = smb + OFF_W2 +
        ((l & 7) + ((l >> 4) << 3)) * 272 + ((l >> 3) & 1) * 16;

    const int fc0 = (l & 3) * 2;
    const int lr = l >> 2;

    for (int mt = 0; mt < 4; mt++) {
        // ---- A fragments: 2 m-frags (f), single fp16 term, coalesced LDG.128 ----
        uint4 hv[2][4];
#pragma unroll
        for (int f = 0; f < 2; f++) {
            const uint32_t* hp = g_srfh + ((size_t)b * 32 + mt * 8 + 2 * w + f) * 512;
#pragma unroll
            for (int t = 0; t < 4; t++)
                hv[f][t] = *(const uint4*)(hp + t * 128 + l * 4);
        }

        // ---- persistent output accumulators (full o = 64) ----
        float D2[2][8][4];
#pragma unroll
        for (int f = 0; f < 2; f++)
#pragma unroll
            for (int q = 0; q < 8; q++)
#pragma unroll
                for (int e = 0; e < 4; e++) D2[f][q][e] = 0.0f;

#pragma unroll
        for (int jh = 0; jh < 2; jh++) {
            // ---- GEMM1: D1[32 m][64 j-half], single-term fp16 ----
            float D1[2][8][4];
#pragma unroll
            for (int f = 0; f < 2; f++)
#pragma unroll
                for (int q = 0; q < 8; q++)
#pragma unroll
                    for (int e = 0; e < 4; e++) D1[f][q][e] = 0.0f;

#pragma unroll
            for (int t = 0; t < 4; t++) {
#pragma unroll
                for (int qq = 0; qq < 4; qq++) {
                    uint32_t bh[4];
                    ldsm4(bh, preB1 + jh * 9216 + qq * 2304 + t * 32);
                    mma16816(D1[0][2 * qq],     (const uint32_t*)&hv[0][t], bh[0], bh[1]);
                    mma16816(D1[0][2 * qq + 1], (const uint32_t*)&hv[0][t], bh[2], bh[3]);
                    mma16816(D1[1][2 * qq],     (const uint32_t*)&hv[1][t], bh[0], bh[1]);
                    mma16816(D1[1][2 * qq + 1], (const uint32_t*)&hv[1][t], bh[2], bh[3]);
                }
            }

            // ---- relu(H + P[dist]) in registers (j-half slice) ----
#pragma unroll
            for (int f = 0; f < 2; f++) {
                const int m_t = mt * 128 + 32 * w + 16 * f + lr;
                const float* P0 = g_P + (size_t)(n - m_t + 512) * HID + jh * 64;
                const float* P1 = P0 - 8 * HID;   // row m_t+8
#pragma unroll
                for (int q = 0; q < 8; q++) {
                    const int jc = 8 * q + fc0;
                    float2 p0 = __ldg((const float2*)(P0 + jc));
                    float2 p1 = __ldg((const float2*)(P1 + jc));
                    D1[f][q][0] = fmaxf(D1[f][q][0] + p0.x, 0.0f);
                    D1[f][q][1] = fmaxf(D1[f][q][1] + p0.y, 0.0f);
                    D1[f][q][2] = fmaxf(D1[f][q][2] + p1.x, 0.0f);
                    D1[f][q][3] = fmaxf(D1[f][q][3] + p1.y, 0.0f);
                }
            }

            // ---- GEMM2 K-partial: D2 += Hrelu(j-half) @ W2(j-half), single-term ----
#pragma unroll
            for (int t2 = 0; t2 < 4; t2++) {
                uint32_t a2[2][4];
#pragma unroll
                for (int f = 0; f < 2; f++) {
                    a2[f][0] = pack2h(D1[f][2 * t2][0],     D1[f][2 * t2][1]);
                    a2[f][1] = pack2h(D1[f][2 * t2][2],     D1[f][2 * t2][3]);
                    a2[f][2] = pack2h(D1[f][2 * t2 + 1][0], D1[f][2 * t2 + 1][1]);
                    a2[f][3] = pack2h(D1[f][2 * t2 + 1][2], D1[f][2 * t2 + 1][3]);
                }
#pragma unroll
                for (int qq = 0; qq < 4; qq++) {
                    uint32_t bh[4];
                    ldsm4(bh, preB2 + jh * 128 + qq * 4352 + t2 * 32);
                    mma16816(D2[0][2 * qq],     a2[0], bh[0], bh[1]);
                    mma16816(D2[0][2 * qq + 1], a2[0], bh[2], bh[3]);
                    mma16816(D2[1][2 * qq],     a2[1], bh[0], bh[1]);
                    mma16816(D2[1][2 * qq + 1], a2[1], bh[2], bh[3]);
                }
            }
        }

        // ---- epilogue: + b2 (from smem), store fp32 ----
#pragma unroll
        for (int f = 0; f < 2; f++) {
            const int m_t = mt * 128 + 32 * w + 16 * f + lr;
            float* ob = out + (((size_t)b * N_ + n) * N_ + m_t) * EMB;
#pragma unroll
            for (int q = 0; q < 8; q++) {
                const int oc = 8 * q + fc0;
                float2 bb = *(const float2*)(b2s + oc);
                *(float2*)(ob + oc) =
                    make_float2(D2[f][q][0] + bb.x, D2[f][q][1] + bb.y);
                *(float2*)(ob + 8 * EMB + oc) =
                    make_float2(D2[f][q][2] + bb.x, D2[f][q][3] + bb.y);
            }
        }
    }
}

// ---------------- launch ----------------
extern "C" void kernel_launch(void* const* d_in, const int* in_sizes, int n_in,
                              void* d_out, int out_size) {
    const float* s       = (const float*)d_in[0];
    const float* W_left  = (const float*)d_in[1];
    const float* b_left  = (const float*)d_in[2];
    const float* W_right = (const float*)d_in[3];
    const float* b_right = (const float*)d_in[4];
    const float* emb     = (const float*)d_in[5];
    const float* W1      = (const float*)d_in[6];
    const float* b1      = (const float*)d_in[7];
    const float* W2      = (const float*)d_in[8];
    const float* b2      = (const float*)d_in[9];
    float* out = (float*)d_out;

    cudaFuncSetAttribute(pair_mma_kernel,
                         cudaFuncAttributeMaxDynamicSharedMemorySize, SMEM_MAIN);

    prologue_kernel<<<128 + 257, 512>>>(s, W_left, b_left, W_right, b_right,
                                        emb, W1, b1, W2);
    pair_mma_kernel<<<dim3(N_, B_), 128, SMEM_MAIN>>>(b2, out);
}